// round 12
// baseline (speedup 1.0000x reference)
#include <cuda_runtime.h>

// HOG layer, fully register-resident: Sobel -> mag + comparison-based 9-bin
// orientation hist -> 8x8 mean pool. No shared memory, no atomics, no syncs.
// Input : x (64,1,512,512) fp32. Output: (64, 9*64*64) fp32.
//
// R12: thread = 2 cols x 8 rows (narrower than R8's 4-col) to cut live
// register state (row structs 24 -> 12 regs) so true demand fits a 48-reg
// cap -> 10 blocks/SM = 40 warps (R8 was allocator-rounded 56->64 regs,
// 32 warps, latency-limited at issue=73%). Binning math identical to R8.
//
// Block = 128 threads = 16 col-groups (32 cols) x 8 row-groups (64 rows).
// Cell = 4 adjacent lanes (8 cols) -> reduce via shfl_xor(1), shfl_xor(2).
//
// Bin math: bin = floor(9*atan2(gx,gy)/pi) mod 9 depends only on
// cot(theta) = gy/gx; monotone predicates p_k = [rat <= cot(k*pi/9)] give
// cumulative sums C_k; bins recovered via bin_b = C_{b-1} - C_{b+1}
// (bin0 = C0 - C1 + C8, bin8 = C7).

#define ORI 9

__device__ __forceinline__ float fsqrt_approx(float v) {
    float y;
    asm("sqrt.approx.f32 %0, %1;" : "=f"(y) : "f"(v));
    return y;
}

struct Row2 { float t0, t1, h0, h1; };

__device__ __forceinline__ Row2 row_filter(float lf, float2 v, float rt) {
    Row2 o;
    o.t0 = lf  - v.y;  o.h0 = fmaf(2.f, v.x, lf)  + v.y;
    o.t1 = v.x - rt;   o.h1 = fmaf(2.f, v.y, v.x) + rt;
    return o;
}

// Unconditional row load (row known in-bounds). Edge predicates are
// loop-invariant so their zero else-values hoist out of the row loop.
__device__ __forceinline__ Row2 load_row(const float* __restrict__ rp,
                                         bool leftEdge, bool rightEdge) {
    float2 v = *reinterpret_cast<const float2*>(rp);
    float lf = leftEdge  ? 0.f : __ldg(rp - 1);
    float rt = rightEdge ? 0.f : __ldg(rp + 2);
    return row_filter(lf, v, rt);
}

// Row load that may be fully out of bounds (zero row). Used twice per thread.
__device__ __forceinline__ Row2 load_row_maybe(const float* __restrict__ rp,
                                               bool valid,
                                               bool leftEdge, bool rightEdge) {
    float2 v = make_float2(0.f, 0.f);
    float lf = 0.f, rt = 0.f;
    if (valid) {
        v = *reinterpret_cast<const float2*>(rp);
        if (!leftEdge)  lf = __ldg(rp - 1);
        if (!rightEdge) rt = __ldg(rp + 2);
    }
    return row_filter(lf, v, rt);
}

// One pixel: accumulate cumulative sums C[0..8].
__device__ __forceinline__ void bin1(float gx, float gy, float* C) {
    // cot(k*pi/9), k = 1..8 (strictly decreasing)
    const float COT[8] = {
         2.7474774194546225f,
         1.1917535925942100f,
         0.5773502691896258f,
         0.1763269807084650f,
        -0.1763269807084650f,
        -0.5773502691896257f,
        -1.1917535925942100f,
        -2.7474774194546230f
    };
    float r2  = fmaf(gx, gx, gy * gy);
    float mag = fsqrt_approx(r2);          // sqrt.approx(0) == 0
    float rat = __fdividef(gy, gx);        // cot(theta); +-inf at gx==0

    C[0] += mag;
    #pragma unroll
    for (int k = 0; k < 8; k++)
        if (rat <= COT[k]) C[k + 1] += mag;
}

__device__ __forceinline__ void bin2(const Row2& a, const Row2& b,
                                     const Row2& c, float* C) {
    float gx0 = fmaf(2.f, b.t0, a.t0) + c.t0;
    float gy0 = a.h0 - c.h0;
    float gx1 = fmaf(2.f, b.t1, a.t1) + c.t1;
    float gy1 = a.h1 - c.h1;
    bin1(gx0, gy0, C);
    bin1(gx1, gy1, C);
}

__global__ __launch_bounds__(128, 10) void hog_kernel(const float* __restrict__ x,
                                                      float* __restrict__ out)
{
    const int n    = blockIdx.z;
    const int row0 = blockIdx.y * 64;
    const int col0 = blockIdx.x * 32;
    const int tid  = threadIdx.x;
    const int cg   = tid & 15;        // col-group (2 cols each), 0..15
    const int rg   = tid >> 4;        // row-group (8 rows each), 0..7

    const int c0 = col0 + cg * 2;     // first output col of this thread
    const int r0 = row0 + rg * 8;     // first output row; r0 in [0, 504]

    const float* __restrict__ img = x + (size_t)n * (512 * 512);
    const float* __restrict__ rp0 = img + r0 * 512 + c0;

    const bool leftEdge  = (c0 == 0);
    const bool rightEdge = (c0 == 510);
    const bool topOK     = (r0 != 0);     // row r0-1 valid?
    const bool botOK     = (r0 != 504);   // row r0+8 valid?

    float C[9];
    #pragma unroll
    for (int b = 0; b < 9; b++) C[b] = 0.0f;

    Row2 a = load_row_maybe(rp0 - 512, topOK, leftEdge, rightEdge);
    Row2 b = load_row(rp0, leftEdge, rightEdge);

    #pragma unroll
    for (int s = 0; s < 7; s++) {
        Row2 c = load_row(rp0 + (s + 1) * 512, leftEdge, rightEdge);
        bin2(a, b, c, C);
        a = b; b = c;
    }
    {   // last step: row r0+8 may be out of bounds
        Row2 c = load_row_maybe(rp0 + 8 * 512, botOK, leftEdge, rightEdge);
        bin2(a, b, c, C);
    }

    // ---- cell reduction: 4 adjacent lanes (cg & ~3 .. | 3) hold one cell ----
    #pragma unroll
    for (int q = 0; q < 9; q++) {
        C[q] += __shfl_xor_sync(0xffffffffu, C[q], 1);
        C[q] += __shfl_xor_sync(0xffffffffu, C[q], 2);
    }

    // ---- recover bins, write pooled output (split 9 bins across 4 lanes) ----
    const int ch = (row0 >> 3) + rg;
    const int cw = (col0 >> 3) + (cg >> 2);
    float* obase = out + (size_t)n * (ORI * 64 * 64) + ch * 64 + cw;

    float bins[9];
    bins[0] = C[0] - C[1] + C[8];
    #pragma unroll
    for (int q = 1; q < 8; q++) bins[q] = C[q - 1] - C[q + 1];
    bins[8] = C[7];

    const int j = cg & 3;
    if (j == 0) {
        obase[0 * 4096] = bins[0] * (1.0f / 64.0f);
        obase[1 * 4096] = bins[1] * (1.0f / 64.0f);
        obase[2 * 4096] = bins[2] * (1.0f / 64.0f);
    } else {
        const int b0 = j * 2 + 1;     // 3,5,7
        obase[b0 * 4096]       = bins[b0]     * (1.0f / 64.0f);
        obase[(b0 + 1) * 4096] = bins[b0 + 1] * (1.0f / 64.0f);
    }
}

extern "C" void kernel_launch(void* const* d_in, const int* in_sizes, int n_in,
                              void* d_out, int out_size)
{
    const float* x   = (const float*)d_in[0];
    float*       out = (float*)d_out;

    dim3 grid(512 / 32, 512 / 64, 64);
    hog_kernel<<<grid, 128>>>(x, out);
}

// round 13
// speedup vs baseline: 1.1617x; 1.1617x over previous
#include <cuda_runtime.h>

// HOG layer, fully register-resident: Sobel -> mag + comparison-based 9-bin
// orientation hist -> 8x8 mean pool. No shared memory, no atomics, no syncs.
// Input : x (64,1,512,512) fp32. Output: (64, 9*64*64) fp32.
//
// Thread = 4 cols x 8 rows patch (inside ONE 8x8 cell). Block = 128 threads
// = 16 col-groups (64 cols) x 8 row-groups (64 rows). Lane l and l^1 cover
// the two column-halves of the same cell -> cell reduce = one shfl.xor(1).
//
// Bin math: bin = floor(9*atan2(gx,gy)/pi) mod 9 depends only on
// cot(theta) = gy/gx; monotone predicates p_k = [rat <= cot(k*pi/9)] give
// cumulative sums C_k; bins recovered via bin_b = C_{b-1} - C_{b+1}
// (bin0 = C0 - C1 + C8, bin8 = C7).
//
// R13 = R8 + dual accumulator banks (even pixels -> C, odd pixels -> D) to
// break the serial conditional-FADD chains on C[k] (4-cyc RAW + 13-cyc
// setp->guard latency), since R5-R12 showed issue% is occupancy-invariant
// (intra-warp dependency bubbles). minblocks 8 -> 7 gives the scheduler a
// 73-reg budget for the ~65-reg natural demand.

#define ORI 9

__device__ __forceinline__ float fsqrt_approx(float v) {
    float y;
    asm("sqrt.approx.f32 %0, %1;" : "=f"(y) : "f"(v));
    return y;
}

struct RowTH { float t[4]; float h[4]; };

__device__ __forceinline__ RowTH row_filter(float lf, float4 v, float rt) {
    RowTH o;
    o.t[0] = lf  - v.y;  o.h[0] = fmaf(2.f, v.x, lf)  + v.y;
    o.t[1] = v.x - v.z;  o.h[1] = fmaf(2.f, v.y, v.x) + v.z;
    o.t[2] = v.y - v.w;  o.h[2] = fmaf(2.f, v.z, v.y) + v.w;
    o.t[3] = v.z - rt;   o.h[3] = fmaf(2.f, v.w, v.z) + rt;
    return o;
}

// Unconditional row load (row known in-bounds). Edge predicates are
// loop-invariant so their zero else-values hoist out of the row loop.
__device__ __forceinline__ RowTH load_row(const float* __restrict__ rp,
                                          bool leftEdge, bool rightEdge) {
    float4 v = *reinterpret_cast<const float4*>(rp);
    float lf = leftEdge  ? 0.f : __ldg(rp - 1);
    float rt = rightEdge ? 0.f : __ldg(rp + 4);
    return row_filter(lf, v, rt);
}

// Row load that may be fully out of bounds (zero row). Used twice per thread.
__device__ __forceinline__ RowTH load_row_maybe(const float* __restrict__ rp,
                                                bool valid,
                                                bool leftEdge, bool rightEdge) {
    float4 v = make_float4(0.f, 0.f, 0.f, 0.f);
    float lf = 0.f, rt = 0.f;
    if (valid) {
        v = *reinterpret_cast<const float4*>(rp);
        if (!leftEdge)  lf = __ldg(rp - 1);
        if (!rightEdge) rt = __ldg(rp + 4);
    }
    return row_filter(lf, v, rt);
}

// One pixel into one accumulator bank.
__device__ __forceinline__ void bin1(float gx, float gy, float* A) {
    // cot(k*pi/9), k = 1..8 (strictly decreasing)
    const float COT[8] = {
         2.7474774194546225f,
         1.1917535925942100f,
         0.5773502691896258f,
         0.1763269807084650f,
        -0.1763269807084650f,
        -0.5773502691896257f,
        -1.1917535925942100f,
        -2.7474774194546230f
    };
    float r2  = fmaf(gx, gx, gy * gy);
    float mag = fsqrt_approx(r2);          // sqrt.approx(0) == 0
    float rat = __fdividef(gy, gx);        // cot(theta); +-inf at gx==0

    A[0] += mag;
    #pragma unroll
    for (int k = 0; k < 8; k++)
        if (rat <= COT[k]) A[k + 1] += mag;
}

// 4 pixels: even pixels accumulate into C, odd into D (independent chains).
__device__ __forceinline__ void bin4(const RowTH& a, const RowTH& b,
                                     const RowTH& c, float* C, float* D) {
    #pragma unroll
    for (int i = 0; i < 4; i++) {
        float gx = fmaf(2.f, b.t[i], a.t[i]) + c.t[i];
        float gy = a.h[i] - c.h[i];
        bin1(gx, gy, (i & 1) ? D : C);
    }
}

__global__ __launch_bounds__(128, 7) void hog_kernel(const float* __restrict__ x,
                                                     float* __restrict__ out)
{
    const int n    = blockIdx.z;
    const int row0 = blockIdx.y * 64;
    const int col0 = blockIdx.x * 64;
    const int tid  = threadIdx.x;
    const int cg   = tid & 15;        // col-group (4 cols each)
    const int rg   = tid >> 4;        // row-group (8 rows each)

    const int c0 = col0 + cg * 4;     // first output col of this thread
    const int r0 = row0 + rg * 8;     // first output row; r0 in [0, 504]

    const float* __restrict__ img = x + (size_t)n * (512 * 512);
    const float* __restrict__ rp0 = img + r0 * 512 + c0;

    const bool leftEdge  = (c0 == 0);
    const bool rightEdge = (c0 == 508);
    const bool topOK     = (r0 != 0);     // row r0-1 valid?
    const bool botOK     = (r0 != 504);   // row r0+8 valid?

    float C[9], D[9];
    #pragma unroll
    for (int b = 0; b < 9; b++) { C[b] = 0.0f; D[b] = 0.0f; }

    RowTH a = load_row_maybe(rp0 - 512, topOK, leftEdge, rightEdge);
    RowTH b = load_row(rp0, leftEdge, rightEdge);

    #pragma unroll
    for (int s = 0; s < 7; s++) {
        RowTH c = load_row(rp0 + (s + 1) * 512, leftEdge, rightEdge);
        bin4(a, b, c, C, D);
        a = b; b = c;
    }
    {   // last step: row r0+8 may be out of bounds
        RowTH c = load_row_maybe(rp0 + 8 * 512, botOK, leftEdge, rightEdge);
        bin4(a, b, c, C, D);
    }

    // merge banks
    #pragma unroll
    for (int q = 0; q < 9; q++) C[q] += D[q];

    // ---- cell reduction: partner lane (lane^1) holds the other 4 columns ----
    #pragma unroll
    for (int q = 0; q < 9; q++)
        C[q] += __shfl_xor_sync(0xffffffffu, C[q], 1);

    // ---- recover bins, write pooled output (split 9 bins across the pair) ----
    const int ch = (row0 >> 3) + rg;
    const int cw = (col0 >> 3) + (cg >> 1);
    float* obase = out + (size_t)n * (ORI * 64 * 64) + ch * 64 + cw;

    float bins[9];
    bins[0] = C[0] - C[1] + C[8];
    #pragma unroll
    for (int q = 1; q < 8; q++) bins[q] = C[q - 1] - C[q + 1];
    bins[8] = C[7];

    if ((cg & 1) == 0) {
        #pragma unroll
        for (int q = 0; q < 5; q++)
            obase[q * 4096] = bins[q] * (1.0f / 64.0f);
    } else {
        #pragma unroll
        for (int q = 5; q < 9; q++)
            obase[q * 4096] = bins[q] * (1.0f / 64.0f);
    }
}

extern "C" void kernel_launch(void* const* d_in, const int* in_sizes, int n_in,
                              void* d_out, int out_size)
{
    const float* x   = (const float*)d_in[0];
    float*       out = (float*)d_out;

    dim3 grid(512 / 64, 512 / 64, 64);
    hog_kernel<<<grid, 128>>>(x, out);
}